// round 13
// baseline (speedup 1.0000x reference)
#include <cuda_runtime.h>
#include <cuda_fp16.h>
#include <cstdint>

// GConvLSTM (ChebConv K=1) fused cell + head, warp-level mma.sync fp16.
// R13 = R11 (best) + (a) c staged coalesced into padded smem, read per-chunk
// via near-conflict-free LDS; (b) B fragment table repacked [n][lane][8w] so
// each n-step loads with LDS.128+LDS.64. Outputs stay scattered-STG (R12
// showed staging them is net-negative).

#define FIN   8
#define HDIM  32
#define OUTD  9
#define TPB   128
#define NPB   128          // nodes per block
#define K48   48           // padded K (41 used: 8 x + 32 h + 1 bias)
#define CPAD  36           // c stage row stride in floats (breaks bank conflicts)

// dynamic smem layout (bytes)
#define SM_B    0                        // 16 n x 32 lane x 8 words x 4B = 16384
#define SM_YB   16384                    // 1024
#define SM_EPI  17408                    // 448 (EpiT = 432)
#define SM_CST  17856                    // 128 x 36 x 4 = 18432
#define SM_A    36288                    // 128 rows x 128B (fp16, swizzled)
#define SM_TOTAL (36288 + 16384)         // 52672

struct EpiT {
    float wci[HDIM], wcf[HDIM], wco[HDIM];
    float bl[12];
};
__device__ __align__(16) uint32_t g_Bfrag[4096];   // [n][lane][slot] fp16x2 (slot 6,7 pad)
__device__ __align__(16) uint32_t g_yB[256];       // [nt][ks][lane][w] fp16x2
__device__ __align__(16) EpiT     g_epi;

// ---------------- math helpers ----------------
__device__ __forceinline__ float fast_ex2(float x) {
    float r; asm("ex2.approx.f32 %0, %1;" : "=f"(r) : "f"(x)); return r;
}
__device__ __forceinline__ float fast_rcp(float x) {
    float r; asm("rcp.approx.f32 %0, %1;" : "=f"(r) : "f"(x)); return r;
}
__device__ __forceinline__ float sigmoid_f(float v) {
    return fast_rcp(1.0f + fast_ex2(-1.4426950408889634f * v));
}
__device__ __forceinline__ float tanh_f(float v) {
    return 1.0f - 2.0f * fast_rcp(1.0f + fast_ex2(2.8853900817779268f * v));
}
__device__ __forceinline__ uint32_t pack_h2(float f0, float f1) {
    __half h0 = __float2half_rn(f0), h1 = __float2half_rn(f1);
    return ((uint32_t)__half_as_ushort(h1) << 16) | __half_as_ushort(h0);
}
__device__ __forceinline__ uint32_t smem_u32(const void* p) {
    uint32_t a;
    asm("{ .reg .u64 t; cvta.to.shared.u64 t, %1; cvt.u32.u64 %0, t; }" : "=r"(a) : "l"(p));
    return a;
}
__device__ __forceinline__ void mma16816(float c[4], const uint32_t a[4],
                                         const uint32_t b[2]) {
    asm volatile(
        "mma.sync.aligned.m16n8k16.row.col.f32.f16.f16.f32 "
        "{%0,%1,%2,%3}, {%4,%5,%6,%7}, {%8,%9}, {%0,%1,%2,%3};"
        : "+f"(c[0]), "+f"(c[1]), "+f"(c[2]), "+f"(c[3])
        : "r"(a[0]), "r"(a[1]), "r"(a[2]), "r"(a[3]), "r"(b[0]), "r"(b[1]));
}
__device__ __forceinline__ void ldmat_x4(uint32_t r[4], uint32_t addr) {
    asm volatile("ldmatrix.sync.aligned.m8n8.x4.shared.b16 {%0,%1,%2,%3}, [%4];"
        : "=r"(r[0]), "=r"(r[1]), "=r"(r[2]), "=r"(r[3]) : "r"(addr));
}
__device__ __forceinline__ void lstm_pw(float si, float sf, float sc, float so,
                                        float cv, float wi, float wf, float wo,
                                        float& hh, float& cc) {
    float ig = sigmoid_f(si + wi * cv);
    float fg = sigmoid_f(sf + wf * cv);
    float tg = tanh_f(sc);
    cc = fg * cv + ig * tg;
    float og = sigmoid_f(so + wo * cc);
    hh = og * tanh_f(cc);
}

// ---------------- prep kernel ----------------
struct PrepArgs {
    const float* Wx[4];
    const float* bx[4];
    const float* Wh[4];
    const float* bh[4];
    const float* b[4];
    const float* wc[4];   // wc[2] dummy
    const float* Wl;
    const float* bl;
};

__global__ void prep_kernel(PrepArgs A) {
    const int gtid = blockIdx.x * blockDim.x + threadIdx.x;
    const int gstr = gridDim.x * blockDim.x;
    // gate B fragments packed [n][lane][slot=ks*2+w] (slots 6,7 zero pad);
    // gate-interleaved columns: column n*8+m -> gate n&3, channel (n>>2)*8+m
    for (int idx = gtid; idx < 4096; idx += gstr) {
        int slot = idx & 7;
        int lane = (idx >> 3) & 31;
        int n    = idx >> 8;
        int ks = slot >> 1, w = slot & 1;
        uint32_t out = 0;
        if (ks < 3) {
            int g = n & 3;
            int j = (n >> 2) * 8 + (lane >> 2);
            int k0 = ks * 16 + (lane & 3) * 2 + w * 8;
            for (int e = 0; e < 2; e++) {
                int k = k0 + e;
                float val = 0.f;
                if (k < FIN)      val = A.Wx[g][k * HDIM + j];
                else if (k < 40)  val = A.Wh[g][(k - FIN) * HDIM + j];
                else if (k == 40) val = A.bx[g][j] + A.bh[g][j] + A.b[g][j];
                out |= (uint32_t)__half_as_ushort(__float2half_rn(val)) << (16 * e);
            }
        }
        g_Bfrag[idx] = out;
    }
    // y-head B fragments: Wl [32 x 9], 2 n-tiles of 8
    for (int idx = gtid; idx < 256; idx += gstr) {
        int w    = idx & 1;
        int lane = (idx >> 1) & 31;
        int ks   = (idx >> 6) & 1;
        int nt   = idx >> 7;
        int n  = nt * 8 + (lane >> 2);
        int k0 = ks * 16 + (lane & 3) * 2 + w * 8;
        uint32_t out = 0;
        for (int e = 0; e < 2; e++) {
            float val = (n < OUTD) ? A.Wl[(k0 + e) * OUTD + n] : 0.f;
            out |= (uint32_t)__half_as_ushort(__float2half_rn(val)) << (16 * e);
        }
        g_yB[idx] = out;
    }
    for (int j = gtid; j < HDIM; j += gstr) {
        g_epi.wci[j] = A.wc[0][j];
        g_epi.wcf[j] = A.wc[1][j];
        g_epi.wco[j] = A.wc[3][j];
    }
    if (gtid < 12)
        g_epi.bl[gtid] = (gtid < OUTD) ? A.bl[gtid] : 0.f;
}

// ---------------- main kernel ----------------
struct Params {
    const float* x;
    const float* h;
    const float* c;
    float* y;
    float* h0;
    float* c0;
    int N;
};

__global__ void __launch_bounds__(TPB, 4)
gconv_lstm_mma_kernel(Params P) {
    extern __shared__ __align__(16) char smem[];
    const uint32_t sbase = smem_u32(smem);
    const int tid = threadIdx.x;
    const int nodeBase = blockIdx.x * NPB;

    // ---- stage B fragments, yB fragments, epilogue tables ----
    {
        const uint4* src = (const uint4*)g_Bfrag;
        uint4* dst = (uint4*)(smem + SM_B);
        for (int i = tid; i < 4096 / 4; i += TPB) dst[i] = src[i];
        if (tid < 64) ((uint4*)(smem + SM_YB))[tid] = ((const uint4*)g_yB)[tid];
        const uint32_t* es = (const uint32_t*)&g_epi;
        uint32_t* ed = (uint32_t*)(smem + SM_EPI);
        if (tid < (int)(sizeof(EpiT) / 4)) ed[tid] = es[tid];
    }

    // ---- stage c coalesced into padded smem rows ----
    {
#pragma unroll
        for (int k = 0; k < 8; k++) {
            int f = k * TPB + tid;          // float4 index
            int n = f >> 3, c4 = f & 7;
            int gn = nodeBase + n;
            int cn = (gn < P.N) ? gn : (P.N - 1);
            float4 v = *(const float4*)(P.c + (size_t)cn * HDIM + c4 * 4);
            *(float4*)(smem + SM_CST + (n * CPAD + c4 * 4) * 4) = v;
        }
    }

    // ---- stage this thread's node row as fp16 A (swizzled 128B rows) ----
    {
        const int sNode = nodeBase + tid;
        const int cls   = (sNode < P.N) ? sNode : (P.N - 1);
        float v[K48];
#pragma unroll
        for (int i = 0; i < K48; i++) v[i] = 0.f;
        const float4* xp = (const float4*)(P.x + (size_t)cls * FIN);
        float4 x0 = xp[0], x1 = xp[1];
        v[0]=x0.x; v[1]=x0.y; v[2]=x0.z; v[3]=x0.w;
        v[4]=x1.x; v[5]=x1.y; v[6]=x1.z; v[7]=x1.w;
        const float4* hp = (const float4*)(P.h + (size_t)cls * HDIM);
#pragma unroll
        for (int i = 0; i < 8; i++) {
            float4 hv = hp[i];
            v[8+4*i]=hv.x; v[9+4*i]=hv.y; v[10+4*i]=hv.z; v[11+4*i]=hv.w;
        }
        v[40] = 1.0f;   // bias column
#pragma unroll
        for (int i = 0; i < 6; i++) {
            uint32_t w[4];
#pragma unroll
            for (int p = 0; p < 4; p++)
                w[p] = pack_h2(v[i * 8 + 2 * p], v[i * 8 + 2 * p + 1]);
            uint32_t off = tid * 128 + ((i * 16) ^ ((tid & 7) << 4));
            *(uint4*)(smem + SM_A + off) = make_uint4(w[0], w[1], w[2], w[3]);
        }
    }
    __syncthreads();

    const EpiT* E = (const EpiT*)(smem + SM_EPI);
    const float* cS = (const float*)(smem + SM_CST);
    const int lane = tid & 31, warp = tid >> 5;
    const int g = lane >> 2, q = lane & 3;

    // node bases per tile (t in {0,1}); node0 = nA[t], node1 = nA[t] + 8
    int nA[2];
    nA[0] = nodeBase + warp * 32 + g;
    nA[1] = nA[0] + 16;
    bool v0[2], v1[2];
#pragma unroll
    for (int t = 0; t < 2; t++) {
        v0[t] = (nA[t] < P.N);
        v1[t] = (nA[t] + 8 < P.N);
    }
    const int lr0 = warp * 32 + g;   // local stage row for tile 0

    // ---- A fragments via ldmatrix (both tiles, persistent) ----
    uint32_t ah[2][3][4];
    {
        const int m = lane >> 3, rl = lane & 7;
        const int seg = m >> 1;
#pragma unroll
        for (int t = 0; t < 2; t++) {
            const int row = warp * 32 + t * 16 + (m & 1) * 8 + rl;
#pragma unroll
            for (int ks = 0; ks < 3; ks++) {
                uint32_t byte = (uint32_t)((ks * 32 + seg * 16) ^ (rl << 4));
                ldmat_x4(ah[t][ks], sbase + SM_A + row * 128 + byte);
            }
        }
    }

    uint32_t yA[2][2][4];   // per tile: y-head A fragments (filled per chunk)

#pragma unroll
    for (int cg = 0; cg < 4; cg++) {
        const int j0 = cg * 8 + q * 2;

        // c reads from padded smem stage (~2-way conflicts)
        float2 cva[2], cvb[2];
#pragma unroll
        for (int t = 0; t < 2; t++) {
            cva[t] = *(const float2*)(cS + (lr0 + t * 16) * CPAD + j0);
            cvb[t] = *(const float2*)(cS + (lr0 + t * 16 + 8) * CPAD + j0);
        }

        // B fragments for the chunk's 4 n-steps (LDS.128 + LDS.64 per step)
        uint32_t bf[4][3][2];
#pragma unroll
        for (int gi = 0; gi < 4; gi++) {
            const char* bp = smem + SM_B + (((cg * 4 + gi) * 32 + lane) * 8) * 4;
            uint4 v = *(const uint4*)bp;
            uint2 u = *(const uint2*)(bp + 16);
            bf[gi][0][0] = v.x; bf[gi][0][1] = v.y;
            bf[gi][1][0] = v.z; bf[gi][1][1] = v.w;
            bf[gi][2][0] = u.x; bf[gi][2][1] = u.y;
        }

        // mma: acc[tile][gate][4]
        float acc[2][4][4];
#pragma unroll
        for (int t = 0; t < 2; t++)
#pragma unroll
            for (int gi = 0; gi < 4; gi++) {
                acc[t][gi][0] = acc[t][gi][1] = acc[t][gi][2] = acc[t][gi][3] = 0.f;
#pragma unroll
                for (int ks = 0; ks < 3; ks++)
                    mma16816(acc[t][gi], ah[t][ks], bf[gi][ks]);
            }

        // peephole weights for this chunk's channels
        const float2 wiv = *(const float2*)(&E->wci[j0]);
        const float2 wfv = *(const float2*)(&E->wcf[j0]);
        const float2 wov = *(const float2*)(&E->wco[j0]);
        const int ks = cg >> 1, w = cg & 1;

#pragma unroll
        for (int t = 0; t < 2; t++) {
            float ha, ca, hb, cb, ha2, ca2, hb2, cb2;
            lstm_pw(acc[t][0][0], acc[t][1][0], acc[t][2][0], acc[t][3][0],
                    cva[t].x, wiv.x, wfv.x, wov.x, ha, ca);
            lstm_pw(acc[t][0][1], acc[t][1][1], acc[t][2][1], acc[t][3][1],
                    cva[t].y, wiv.y, wfv.y, wov.y, hb, cb);
            lstm_pw(acc[t][0][2], acc[t][1][2], acc[t][2][2], acc[t][3][2],
                    cvb[t].x, wiv.x, wfv.x, wov.x, ha2, ca2);
            lstm_pw(acc[t][0][3], acc[t][1][3], acc[t][2][3], acc[t][3][3],
                    cvb[t].y, wiv.y, wfv.y, wov.y, hb2, cb2);
            if (v0[t]) {
                *(float2*)(P.h0 + (size_t)nA[t] * HDIM + j0) = make_float2(ha, hb);
                *(float2*)(P.c0 + (size_t)nA[t] * HDIM + j0) = make_float2(ca, cb);
            }
            if (v1[t]) {
                *(float2*)(P.h0 + (size_t)(nA[t] + 8) * HDIM + j0) = make_float2(ha2, hb2);
                *(float2*)(P.c0 + (size_t)(nA[t] + 8) * HDIM + j0) = make_float2(ca2, cb2);
            }
            yA[t][ks][2 * w + 0] = pack_h2(fmaxf(ha, 0.f),  fmaxf(hb, 0.f));
            yA[t][ks][2 * w + 1] = pack_h2(fmaxf(ha2, 0.f), fmaxf(hb2, 0.f));
        }
    }

    // ---- y-head mma: per tile, 2 n-tiles x 2 ksteps ----
    const float2 blq = *(const float2*)(&E->bl[2 * q]);
    const float  bl8 = E->bl[8];
#pragma unroll
    for (int t = 0; t < 2; t++) {
        float yacc0[4] = {0.f, 0.f, 0.f, 0.f};
        float yacc1[4] = {0.f, 0.f, 0.f, 0.f};
#pragma unroll
        for (int ks = 0; ks < 2; ks++) {
            uint2 b0 = *(const uint2*)(smem + SM_YB + ((0 * 2 + ks) * 32 + lane) * 8);
            uint2 b1 = *(const uint2*)(smem + SM_YB + ((1 * 2 + ks) * 32 + lane) * 8);
            uint32_t bb0[2] = {b0.x, b0.y};
            uint32_t bb1[2] = {b1.x, b1.y};
            mma16816(yacc0, yA[t][ks], bb0);
            mma16816(yacc1, yA[t][ks], bb1);
        }
        if (v0[t]) {
            float* oy = P.y + (size_t)nA[t] * OUTD;
            oy[2 * q]     = yacc0[0] + blq.x;
            oy[2 * q + 1] = yacc0[1] + blq.y;
            if (q == 0) oy[8] = yacc1[0] + bl8;
        }
        if (v1[t]) {
            float* oy = P.y + (size_t)(nA[t] + 8) * OUTD;
            oy[2 * q]     = yacc0[2] + blq.x;
            oy[2 * q + 1] = yacc0[3] + blq.y;
            if (q == 0) oy[8] = yacc1[2] + bl8;
        }
    }
}

extern "C" void kernel_launch(void* const* d_in, const int* in_sizes, int n_in,
                              void* d_out, int out_size) {
    (void)n_in; (void)out_size;

    PrepArgs A;
    const int wx_idx[4] = {5, 11, 17, 22};   // gate order: i, f, c, o
    for (int g = 0; g < 4; g++) {
        int base = wx_idx[g];
        A.Wx[g] = (const float*)d_in[base + 0];
        A.bx[g] = (const float*)d_in[base + 1];
        A.Wh[g] = (const float*)d_in[base + 2];
        A.bh[g] = (const float*)d_in[base + 3];
        A.b[g]  = (const float*)d_in[base + 4];
        A.wc[g] = (g == 2) ? A.b[g] : (const float*)d_in[base + 5];  // dummy for gate c
    }
    A.Wl = (const float*)d_in[28];
    A.bl = (const float*)d_in[29];

    Params P;
    P.x = (const float*)d_in[0];
    // d_in[1] = edge_index, d_in[2] = edge_weight: unused (ChebConv K=1)
    P.h = (const float*)d_in[3];
    P.c = (const float*)d_in[4];

    const int N = in_sizes[0] / FIN;
    P.N = N;
    float* out = (float*)d_out;
    P.y  = out;
    P.h0 = out + (size_t)N * OUTD;
    P.c0 = out + (size_t)N * (OUTD + HDIM);

    prep_kernel<<<16, 256>>>(A);

    cudaFuncSetAttribute(gconv_lstm_mma_kernel,
                         cudaFuncAttributeMaxDynamicSharedMemorySize, SM_TOTAL);
    const int grid = (N + NPB - 1) / NPB;
    gconv_lstm_mma_kernel<<<grid, TPB, SM_TOTAL>>>(P);
}

// round 14
// speedup vs baseline: 1.1988x; 1.1988x over previous
#include <cuda_runtime.h>
#include <cuda_fp16.h>
#include <cstdint>

// GConvLSTM (ChebConv K=1) fused cell + head, warp-level mma.sync fp16.
// R14 = R11 (best: gate-interleaved B, chunked epilogue, B shared across
// tiles) + __restrict__/__ldg + double-buffered c prefetch so the scattered
// c loads (240-580 cyc) are issued one chunk ahead and hide under the mmas.

#define FIN   8
#define HDIM  32
#define OUTD  9
#define TPB   128
#define NPB   128          // nodes per block
#define K48   48           // padded K (41 used: 8 x + 32 h + 1 bias)

// dynamic smem layout (bytes)
#define SM_A    0                        // 128 rows x 128B (fp16, swizzled)
#define SM_B    16384                    // 3 ks x 16 n x 32 lanes x 8B = 12288
#define SM_YB   (16384 + 12288)          // 28672: 2 nt x 2 ks x 32 x 8B = 1024
#define SM_EPI  (28672 + 1024)           // 29696
#define SM_TOTAL (29696 + 432)

struct EpiT {
    float wci[HDIM], wcf[HDIM], wco[HDIM];
    float bl[12];
};
__device__ __align__(16) uint32_t g_Bfrag[3072];   // [ks][n][lane][w] fp16x2
__device__ __align__(16) uint32_t g_yB[256];       // [nt][ks][lane][w] fp16x2
__device__ __align__(16) EpiT     g_epi;

// ---------------- math helpers ----------------
__device__ __forceinline__ float fast_ex2(float x) {
    float r; asm("ex2.approx.f32 %0, %1;" : "=f"(r) : "f"(x)); return r;
}
__device__ __forceinline__ float fast_rcp(float x) {
    float r; asm("rcp.approx.f32 %0, %1;" : "=f"(r) : "f"(x)); return r;
}
__device__ __forceinline__ float sigmoid_f(float v) {
    return fast_rcp(1.0f + fast_ex2(-1.4426950408889634f * v));
}
__device__ __forceinline__ float tanh_f(float v) {
    return 1.0f - 2.0f * fast_rcp(1.0f + fast_ex2(2.8853900817779268f * v));
}
__device__ __forceinline__ uint32_t pack_h2(float f0, float f1) {
    __half h0 = __float2half_rn(f0), h1 = __float2half_rn(f1);
    return ((uint32_t)__half_as_ushort(h1) << 16) | __half_as_ushort(h0);
}
__device__ __forceinline__ uint32_t smem_u32(const void* p) {
    uint32_t a;
    asm("{ .reg .u64 t; cvta.to.shared.u64 t, %1; cvt.u32.u64 %0, t; }" : "=r"(a) : "l"(p));
    return a;
}
__device__ __forceinline__ void mma16816(float c[4], const uint32_t a[4],
                                         const uint32_t b[2]) {
    asm volatile(
        "mma.sync.aligned.m16n8k16.row.col.f32.f16.f16.f32 "
        "{%0,%1,%2,%3}, {%4,%5,%6,%7}, {%8,%9}, {%0,%1,%2,%3};"
        : "+f"(c[0]), "+f"(c[1]), "+f"(c[2]), "+f"(c[3])
        : "r"(a[0]), "r"(a[1]), "r"(a[2]), "r"(a[3]), "r"(b[0]), "r"(b[1]));
}
__device__ __forceinline__ void ldmat_x4(uint32_t r[4], uint32_t addr) {
    asm volatile("ldmatrix.sync.aligned.m8n8.x4.shared.b16 {%0,%1,%2,%3}, [%4];"
        : "=r"(r[0]), "=r"(r[1]), "=r"(r[2]), "=r"(r[3]) : "r"(addr));
}
__device__ __forceinline__ void lstm_pw(float si, float sf, float sc, float so,
                                        float cv, float wi, float wf, float wo,
                                        float& hh, float& cc) {
    float ig = sigmoid_f(si + wi * cv);
    float fg = sigmoid_f(sf + wf * cv);
    float tg = tanh_f(sc);
    cc = fg * cv + ig * tg;
    float og = sigmoid_f(so + wo * cc);
    hh = og * tanh_f(cc);
}

// ---------------- prep kernel ----------------
struct PrepArgs {
    const float* Wx[4];
    const float* bx[4];
    const float* Wh[4];
    const float* bh[4];
    const float* b[4];
    const float* wc[4];   // wc[2] dummy
    const float* Wl;
    const float* bl;
};

__global__ void prep_kernel(PrepArgs A) {
    const int gtid = blockIdx.x * blockDim.x + threadIdx.x;
    const int gstr = gridDim.x * blockDim.x;
    // gate B fragments, mma lane order, gate-interleaved columns:
    // column n*8+m -> gate = n&3, channel j = (n>>2)*8 + m
    for (int idx = gtid; idx < 3072; idx += gstr) {
        int w    = idx & 1;
        int lane = (idx >> 1) & 31;
        int n    = (idx >> 6) & 15;
        int ks   = idx >> 10;
        int g = n & 3;
        int j = (n >> 2) * 8 + (lane >> 2);
        int k0 = ks * 16 + (lane & 3) * 2 + w * 8;
        uint32_t out = 0;
        for (int e = 0; e < 2; e++) {
            int k = k0 + e;
            float val = 0.f;
            if (k < FIN)      val = A.Wx[g][k * HDIM + j];
            else if (k < 40)  val = A.Wh[g][(k - FIN) * HDIM + j];
            else if (k == 40) val = A.bx[g][j] + A.bh[g][j] + A.b[g][j];
            out |= (uint32_t)__half_as_ushort(__float2half_rn(val)) << (16 * e);
        }
        g_Bfrag[idx] = out;
    }
    // y-head B fragments: Wl [32 x 9], 2 n-tiles of 8
    for (int idx = gtid; idx < 256; idx += gstr) {
        int w    = idx & 1;
        int lane = (idx >> 1) & 31;
        int ks   = (idx >> 6) & 1;
        int nt   = idx >> 7;
        int n  = nt * 8 + (lane >> 2);
        int k0 = ks * 16 + (lane & 3) * 2 + w * 8;
        uint32_t out = 0;
        for (int e = 0; e < 2; e++) {
            float val = (n < OUTD) ? A.Wl[(k0 + e) * OUTD + n] : 0.f;
            out |= (uint32_t)__half_as_ushort(__float2half_rn(val)) << (16 * e);
        }
        g_yB[idx] = out;
    }
    for (int j = gtid; j < HDIM; j += gstr) {
        g_epi.wci[j] = A.wc[0][j];
        g_epi.wcf[j] = A.wc[1][j];
        g_epi.wco[j] = A.wc[3][j];
    }
    if (gtid < 12)
        g_epi.bl[gtid] = (gtid < OUTD) ? A.bl[gtid] : 0.f;
}

// ---------------- main kernel ----------------
struct Params {
    const float* __restrict__ x;
    const float* __restrict__ h;
    const float* __restrict__ c;
    float* __restrict__ y;
    float* __restrict__ h0;
    float* __restrict__ c0;
    int N;
};

__global__ void __launch_bounds__(TPB, 4)
gconv_lstm_mma_kernel(Params P) {
    extern __shared__ __align__(16) char smem[];
    const uint32_t sbase = smem_u32(smem);
    const int tid = threadIdx.x;

    // ---- stage B fragments, yB fragments, epilogue tables ----
    {
        const uint4* src = (const uint4*)g_Bfrag;
        uint4* dst = (uint4*)(smem + SM_B);
        for (int i = tid; i < 3072 / 4; i += TPB) dst[i] = src[i];
        if (tid < 64) ((uint4*)(smem + SM_YB))[tid] = ((const uint4*)g_yB)[tid];
        const uint32_t* es = (const uint32_t*)&g_epi;
        uint32_t* ed = (uint32_t*)(smem + SM_EPI);
        if (tid < (int)(sizeof(EpiT) / 4)) ed[tid] = es[tid];
    }

    // ---- stage this thread's node row as fp16 A (swizzled 128B rows) ----
    {
        const int sNode = blockIdx.x * NPB + tid;
        const int cls   = (sNode < P.N) ? sNode : (P.N - 1);
        float v[K48];
#pragma unroll
        for (int i = 0; i < K48; i++) v[i] = 0.f;
        const float4* xp = (const float4*)(P.x + (size_t)cls * FIN);
        float4 x0 = __ldg(xp), x1 = __ldg(xp + 1);
        v[0]=x0.x; v[1]=x0.y; v[2]=x0.z; v[3]=x0.w;
        v[4]=x1.x; v[5]=x1.y; v[6]=x1.z; v[7]=x1.w;
        const float4* hp = (const float4*)(P.h + (size_t)cls * HDIM);
#pragma unroll
        for (int i = 0; i < 8; i++) {
            float4 hv = __ldg(hp + i);
            v[8+4*i]=hv.x; v[9+4*i]=hv.y; v[10+4*i]=hv.z; v[11+4*i]=hv.w;
        }
        v[40] = 1.0f;   // bias column
#pragma unroll
        for (int i = 0; i < 6; i++) {
            uint32_t w[4];
#pragma unroll
            for (int p = 0; p < 4; p++)
                w[p] = pack_h2(v[i * 8 + 2 * p], v[i * 8 + 2 * p + 1]);
            uint32_t off = tid * 128 + ((i * 16) ^ ((tid & 7) << 4));
            *(uint4*)(smem + SM_A + off) = make_uint4(w[0], w[1], w[2], w[3]);
        }
    }
    __syncthreads();

    const EpiT* E = (const EpiT*)(smem + SM_EPI);
    const int lane = tid & 31, warp = tid >> 5;
    const int g = lane >> 2, q = lane & 3;

    // node bases per tile (t in {0,1}); node0 = nA[t], node1 = nA[t] + 8
    int nA[2];
    nA[0] = blockIdx.x * NPB + warp * 32 + g;
    nA[1] = nA[0] + 16;
    bool v0[2], v1[2];
    const float* cp0[2];
    const float* cp1[2];
#pragma unroll
    for (int t = 0; t < 2; t++) {
        v0[t] = (nA[t] < P.N);
        v1[t] = (nA[t] + 8 < P.N);
        cp0[t] = P.c + (size_t)(v0[t] ? nA[t] : (P.N - 1)) * HDIM;
        cp1[t] = P.c + (size_t)(v1[t] ? (nA[t] + 8) : (P.N - 1)) * HDIM;
    }

    // ---- A fragments via ldmatrix (both tiles, persistent) ----
    uint32_t ah[2][3][4];
    {
        const int m = lane >> 3, rl = lane & 7;
        const int seg = m >> 1;
#pragma unroll
        for (int t = 0; t < 2; t++) {
            const int row = warp * 32 + t * 16 + (m & 1) * 8 + rl;
#pragma unroll
            for (int ks = 0; ks < 3; ks++) {
                uint32_t byte = (uint32_t)((ks * 32 + seg * 16) ^ (rl << 4));
                ldmat_x4(ah[t][ks], sbase + SM_A + row * 128 + byte);
            }
        }
    }

    uint32_t yA[2][2][4];   // per tile: y-head A fragments (filled per chunk)

    // ---- double-buffered c prefetch: issue chunk 0 now ----
    float2 cva[2], cvb[2];
#pragma unroll
    for (int t = 0; t < 2; t++) {
        cva[t] = __ldg((const float2*)(cp0[t] + q * 2));
        cvb[t] = __ldg((const float2*)(cp1[t] + q * 2));
    }

#pragma unroll
    for (int cg = 0; cg < 4; cg++) {
        const int j0 = cg * 8 + q * 2;

        // prefetch next chunk's c (hidden under this chunk's mma block)
        float2 nva[2], nvb[2];
        if (cg < 3) {
            const int jn = (cg + 1) * 8 + q * 2;
#pragma unroll
            for (int t = 0; t < 2; t++) {
                nva[t] = __ldg((const float2*)(cp0[t] + jn));
                nvb[t] = __ldg((const float2*)(cp1[t] + jn));
            }
        }

        // B fragments for the chunk's 4 n-steps (shared by both tiles)
        uint32_t bf[4][3][2];
#pragma unroll
        for (int gi = 0; gi < 4; gi++)
#pragma unroll
            for (int ks = 0; ks < 3; ks++) {
                uint2 hv = *(const uint2*)(smem + SM_B +
                            ((ks * 16 + cg * 4 + gi) * 32 + lane) * 8);
                bf[gi][ks][0] = hv.x; bf[gi][ks][1] = hv.y;
            }

        // mma: acc[tile][gate][4]
        float acc[2][4][4];
#pragma unroll
        for (int t = 0; t < 2; t++)
#pragma unroll
            for (int gi = 0; gi < 4; gi++) {
                acc[t][gi][0] = acc[t][gi][1] = acc[t][gi][2] = acc[t][gi][3] = 0.f;
#pragma unroll
                for (int ks = 0; ks < 3; ks++)
                    mma16816(acc[t][gi], ah[t][ks], bf[gi][ks]);
            }

        // peephole weights for this chunk's channels
        const float2 wiv = *(const float2*)(&E->wci[j0]);
        const float2 wfv = *(const float2*)(&E->wcf[j0]);
        const float2 wov = *(const float2*)(&E->wco[j0]);
        const int ks = cg >> 1, w = cg & 1;

#pragma unroll
        for (int t = 0; t < 2; t++) {
            float ha, ca, hb, cb, ha2, ca2, hb2, cb2;
            lstm_pw(acc[t][0][0], acc[t][1][0], acc[t][2][0], acc[t][3][0],
                    cva[t].x, wiv.x, wfv.x, wov.x, ha, ca);
            lstm_pw(acc[t][0][1], acc[t][1][1], acc[t][2][1], acc[t][3][1],
                    cva[t].y, wiv.y, wfv.y, wov.y, hb, cb);
            lstm_pw(acc[t][0][2], acc[t][1][2], acc[t][2][2], acc[t][3][2],
                    cvb[t].x, wiv.x, wfv.x, wov.x, ha2, ca2);
            lstm_pw(acc[t][0][3], acc[t][1][3], acc[t][2][3], acc[t][3][3],
                    cvb[t].y, wiv.y, wfv.y, wov.y, hb2, cb2);
            if (v0[t]) {
                *(float2*)(P.h0 + (size_t)nA[t] * HDIM + j0) = make_float2(ha, hb);
                *(float2*)(P.c0 + (size_t)nA[t] * HDIM + j0) = make_float2(ca, cb);
            }
            if (v1[t]) {
                *(float2*)(P.h0 + (size_t)(nA[t] + 8) * HDIM + j0) = make_float2(ha2, hb2);
                *(float2*)(P.c0 + (size_t)(nA[t] + 8) * HDIM + j0) = make_float2(ca2, cb2);
            }
            yA[t][ks][2 * w + 0] = pack_h2(fmaxf(ha, 0.f),  fmaxf(hb, 0.f));
            yA[t][ks][2 * w + 1] = pack_h2(fmaxf(ha2, 0.f), fmaxf(hb2, 0.f));
        }

        if (cg < 3) {
#pragma unroll
            for (int t = 0; t < 2; t++) { cva[t] = nva[t]; cvb[t] = nvb[t]; }
        }
    }

    // ---- y-head mma: per tile, 2 n-tiles x 2 ksteps ----
    const float2 blq = *(const float2*)(&E->bl[2 * q]);
    const float  bl8 = E->bl[8];
#pragma unroll
    for (int t = 0; t < 2; t++) {
        float yacc0[4] = {0.f, 0.f, 0.f, 0.f};
        float yacc1[4] = {0.f, 0.f, 0.f, 0.f};
#pragma unroll
        for (int ks = 0; ks < 2; ks++) {
            uint2 b0 = *(const uint2*)(smem + SM_YB + ((0 * 2 + ks) * 32 + lane) * 8);
            uint2 b1 = *(const uint2*)(smem + SM_YB + ((1 * 2 + ks) * 32 + lane) * 8);
            uint32_t bb0[2] = {b0.x, b0.y};
            uint32_t bb1[2] = {b1.x, b1.y};
            mma16816(yacc0, yA[t][ks], bb0);
            mma16816(yacc1, yA[t][ks], bb1);
        }
        if (v0[t]) {
            float* oy = P.y + (size_t)nA[t] * OUTD;
            oy[2 * q]     = yacc0[0] + blq.x;
            oy[2 * q + 1] = yacc0[1] + blq.y;
            if (q == 0) oy[8] = yacc1[0] + bl8;
        }
        if (v1[t]) {
            float* oy = P.y + (size_t)(nA[t] + 8) * OUTD;
            oy[2 * q]     = yacc0[2] + blq.x;
            oy[2 * q + 1] = yacc0[3] + blq.y;
            if (q == 0) oy[8] = yacc1[2] + bl8;
        }
    }
}

extern "C" void kernel_launch(void* const* d_in, const int* in_sizes, int n_in,
                              void* d_out, int out_size) {
    (void)n_in; (void)out_size;

    PrepArgs A;
    const int wx_idx[4] = {5, 11, 17, 22};   // gate order: i, f, c, o
    for (int g = 0; g < 4; g++) {
        int base = wx_idx[g];
        A.Wx[g] = (const float*)d_in[base + 0];
        A.bx[g] = (const float*)d_in[base + 1];
        A.Wh[g] = (const float*)d_in[base + 2];
        A.bh[g] = (const float*)d_in[base + 3];
        A.b[g]  = (const float*)d_in[base + 4];
        A.wc[g] = (g == 2) ? A.b[g] : (const float*)d_in[base + 5];  // dummy for gate c
    }
    A.Wl = (const float*)d_in[28];
    A.bl = (const float*)d_in[29];

    Params P;
    P.x = (const float*)d_in[0];
    // d_in[1] = edge_index, d_in[2] = edge_weight: unused (ChebConv K=1)
    P.h = (const float*)d_in[3];
    P.c = (const float*)d_in[4];

    const int N = in_sizes[0] / FIN;
    P.N = N;
    float* out = (float*)d_out;
    P.y  = out;
    P.h0 = out + (size_t)N * OUTD;
    P.c0 = out + (size_t)N * (OUTD + HDIM);

    prep_kernel<<<16, 256>>>(A);

    cudaFuncSetAttribute(gconv_lstm_mma_kernel,
                         cudaFuncAttributeMaxDynamicSharedMemorySize, SM_TOTAL);
    const int grid = (N + NPB - 1) / NPB;
    gconv_lstm_mma_kernel<<<grid, TPB, SM_TOTAL>>>(P);
}